// round 11
// baseline (speedup 1.0000x reference)
#include <cuda_runtime.h>

// CoupledClustersLossV2 — balanced persistent partition, cheap cross-CTA combine.
// embeddings: [256 cls][2 pos/neg][32 samples][2048] fp32 = 128 MB.
// ||x - a||^2 = ||x||^2 - (x·s)/16 + ||s||^2/1024,  s = sum of 32 pos rows.
//
// R10 (1 CTA/class, 29.4us) left 1.18x wave imbalance (2-class SMs vs 865KB
// ideal). Here the flat 4096-chunk space is split evenly over 296 CTAs
// (14 chunks for bids 0-247, 13 for 248-295 -> 1.035 balance). Each class has
// 2-3 statically-determined contributors; per-run flushes are cheap (wsums +
// fire-and-forget STG + 1 bar; fence+atomic on warp0 hidden under next chunk).
// Chunk loop is R10's proven machinery: self-visible cp.async (each thread
// copies exactly the slots it reads -> no tile barrier), 3 stages, one
// barrier/chunk (column-sum exchange). All reductions fixed-order.

#define NCLS     256
#define NS       32
#define DIM      2048
#define CHUNK    128
#define THREADS  256
#define GRID     296
#define NBIG     248                  // bids 0..247 take 14 chunks, rest 13
#define BIGSTART 3472                 // 14 * 248
#define NSTAGE   3
#define TILE_F4  2048                 // 64 rows x 32 float4 = 32KB
#define SMEM_BYTES (NSTAGE * TILE_F4 * 16 + 2 * 8 * CHUNK * 4)   // 102400
#define ROW_F4   (DIM / 4)            // 512
#define MARGIN   0.3f

// per-(class, slot) row partials: 0=||pos||^2 1=pos·s 2=||neg||^2 3=neg·s
__device__ float        g_scratch[NCLS][3][4][NS];
__device__ unsigned int g_done[NCLS];      // epoch counters (never reset)
__device__ float        g_class_loss[NCLS];
__device__ unsigned int g_cls_done;        // epoch counter (never reset)

__device__ __forceinline__ float dot4(float4 a, float4 b) {
    return fmaf(a.x, b.x, fmaf(a.y, b.y, fmaf(a.z, b.z, a.w * b.w)));
}
__device__ __forceinline__ float wsum(float v) {
#pragma unroll
    for (int o = 16; o > 0; o >>= 1) v += __shfl_xor_sync(0xffffffffu, v, o);
    return v;
}
__device__ __forceinline__ void cp_async16(unsigned smem_dst, const float4* gsrc) {
    asm volatile("cp.async.cg.shared.global [%0], [%1], 16;\n"
                 :: "r"(smem_dst), "l"(gsrc));
}
// Which CTA owns global chunk x (static partition inverse).
__device__ __forceinline__ int cta_of(int x) {
    return (x < BIGSTART) ? (x / 14) : (NBIG + (x - BIGSTART) / 13);
}

__global__ __launch_bounds__(THREADS, 2)
void ccl_kernel(const float* __restrict__ emb, float* __restrict__ out)
{
    extern __shared__ float4 sh4[];                       // [NSTAGE][TILE_F4]
    float* spart = (float*)(sh4 + NSTAGE * TILE_F4);      // [2][8][CHUNK]

    const int bid  = blockIdx.x;
    const int tid  = threadIdx.x;
    const int warp = tid >> 5;
    const int lane = tid & 31;

    const int c0  = (bid < NBIG) ? 14 * bid : BIGSTART + 13 * (bid - NBIG);
    const int nch = (bid < NBIG) ? 14 : 13;

    // This thread's fixed tile slots: pos rows warp+8i, neg rows 32+warp+8i.
    const unsigned slot0  = (unsigned)((warp * 32 + lane) * 16);
    const unsigned smbase = (unsigned)__cvta_generic_to_shared(sh4);
    const float4*  tbase  = (const float4*)emb + (size_t)warp * ROW_F4 + lane;

    // Issue global chunk x into stage (j % 3); self-slots only.
    auto issue = [&](int j) {
        const int x   = c0 + j;
        const float4* g = tbase + ((size_t)(x >> 4) << 15)   // class * 2*NS*DIM/4
                        + ((x & 15) << 5);                   // chunk col offset
        const unsigned sb = smbase + (unsigned)(j % NSTAGE) * (TILE_F4 * 16);
#pragma unroll
        for (int i = 0; i < 4; ++i)
            cp_async16(sb + slot0 + i * 4096u, g + (size_t)(i * 8) * ROW_F4);
#pragma unroll
        for (int i = 0; i < 4; ++i)
            cp_async16(sb + 16384u + slot0 + i * 4096u,
                       g + (size_t)(NS + i * 8) * ROW_F4);
        asm volatile("cp.async.commit_group;\n" ::);
    };

    issue(0); issue(1); issue(2);

    float pn[4] = {0.f,0.f,0.f,0.f};
    float tp[4] = {0.f,0.f,0.f,0.f};
    float nn[4] = {0.f,0.f,0.f,0.f};
    float tn[4] = {0.f,0.f,0.f,0.f};

    for (int j = 0; j < nch; ++j) {
        const int sb = j & 1;
        const float4* tile = sh4 + (j % NSTAGE) * TILE_F4;

        // Self-visibility: we read only our own copies -> no barrier needed.
        if (j + 2 < nch)      asm volatile("cp.async.wait_group 2;\n" ::);
        else if (j + 1 < nch) asm volatile("cp.async.wait_group 1;\n" ::);
        else                  asm volatile("cp.async.wait_group 0;\n" ::);

        float4 p[4], n[4];
#pragma unroll
        for (int i = 0; i < 4; ++i) {
            p[i] = tile[(warp + i * 8) * 32 + lane];
            n[i] = tile[(32 + warp + i * 8) * 32 + lane];
        }

        // Norms + per-warp column-sum partial.
#pragma unroll
        for (int i = 0; i < 4; ++i) {
            pn[i] += dot4(p[i], p[i]);
            nn[i] += dot4(n[i], n[i]);
        }
        float4 spv;
        spv.x = (p[0].x + p[1].x) + (p[2].x + p[3].x);
        spv.y = (p[0].y + p[1].y) + (p[2].y + p[3].y);
        spv.z = (p[0].z + p[1].z) + (p[2].z + p[3].z);
        spv.w = (p[0].w + p[1].w) + (p[2].w + p[3].w);
        *(float4*)&spart[(sb * 8 + warp) * CHUNK + lane * 4] = spv;

        __syncthreads();   // the ONLY per-chunk barrier (colsum exchange)

        if (j + 3 < nch) issue(j + 3);   // refill our own consumed slots

        float4 sc = *(const float4*)&spart[(sb * 8 + 0) * CHUNK + lane * 4];
#pragma unroll
        for (int w = 1; w < 8; ++w) {
            float4 t = *(const float4*)&spart[(sb * 8 + w) * CHUNK + lane * 4];
            sc.x += t.x; sc.y += t.y; sc.z += t.z; sc.w += t.w;
        }
#pragma unroll
        for (int i = 0; i < 4; ++i) {
            tp[i] += dot4(p[i], sc);
            tn[i] += dot4(n[i], sc);
        }

        // ---- class-run boundary: flush partials (cheap) ----
        const int x = c0 + j;
        if (((x + 1) & 15) == 0 || j == nch - 1) {
            const int cls  = x >> 4;
            const int b0   = cta_of(cls << 4);
            const int slot = bid - b0;                  // 0..2
#pragma unroll
            for (int i = 0; i < 4; ++i) {
                const float a = wsum(pn[i]);
                const float b = wsum(tp[i]);
                const float d = wsum(nn[i]);
                const float e = wsum(tn[i]);
                if (lane == 0) {
                    const int row = warp + i * 8;
                    g_scratch[cls][slot][0][row] = a;
                    g_scratch[cls][slot][1][row] = b;
                    g_scratch[cls][slot][2][row] = d;
                    g_scratch[cls][slot][3][row] = e;
                }
                pn[i] = tp[i] = nn[i] = tn[i] = 0.f;    // next class run
            }
            __syncthreads();     // all 32 scratch rows issued before the count

            if (warp == 0) {     // warps 1-7 resume streaming immediately
                const int exp = cta_of((cls << 4) + 15) - b0 + 1;   // 2 or 3
                unsigned fin = 0;
                if (lane == 0) {
                    __threadfence();                    // publish scratch
                    const unsigned old = atomicAdd(&g_done[cls], 1u);
                    fin = ((old % (unsigned)exp) == (unsigned)(exp - 1)) ? 1u : 0u;
                }
                fin = __shfl_sync(0xffffffffu, fin, 0);
                if (fin) {
                    // ---- per-class finisher ----
                    __threadfence();
                    float fpn = 0.f, ftp = 0.f, fnn = 0.f, ftn = 0.f;
#pragma unroll
                    for (int s = 0; s < 3; ++s) {       // fixed order
                        if (s < exp) {
                            fpn += __ldcg(&g_scratch[cls][s][0][lane]);
                            ftp += __ldcg(&g_scratch[cls][s][1][lane]);
                            fnn += __ldcg(&g_scratch[cls][s][2][lane]);
                            ftn += __ldcg(&g_scratch[cls][s][3][lane]);
                        }
                    }
                    const float ssum  = wsum(ftp);              // ||s||^2
                    const float anorm = ssum * (1.0f / 1024.0f);
                    const float ap2   = fpn - ftp * (1.0f / 16.0f) + anorm;
                    const float nd2   = fnn - ftn * (1.0f / 16.0f) + anorm;

                    float mn = nd2;
#pragma unroll
                    for (int o = 16; o > 0; o >>= 1)
                        mn = fminf(mn, __shfl_xor_sync(0xffffffffu, mn, o));
                    const float an = sqrtf(fmaxf(mn, 0.f));

                    float t = fmaxf(sqrtf(fmaxf(ap2, 0.f)) - an + MARGIN, 0.f);
                    const float term = wsum(t * t);

                    unsigned old2 = 0;
                    if (lane == 0) {
                        g_class_loss[cls] = term;
                        __threadfence();
                        old2 = atomicAdd(&g_cls_done, 1u);
                    }
                    old2 = __shfl_sync(0xffffffffu, old2, 0);
                    if ((old2 & (NCLS - 1u)) == (NCLS - 1u)) {
                        // ---- global finisher: fixed-order mean ----
                        __threadfence();
                        float v = 0.f;
#pragma unroll
                        for (int q = 0; q < NCLS / 32; ++q)
                            v += __ldcg(&g_class_loss[q * 32 + lane]);
                        v = wsum(v);
                        if (lane == 0) out[0] = v * (1.0f / (float)NCLS);
                    }
                }
            }
        }
    }
}

extern "C" void kernel_launch(void* const* d_in, const int* in_sizes, int n_in,
                              void* d_out, int out_size)
{
    (void)in_sizes; (void)n_in; (void)out_size;
    const float* emb = (const float*)d_in[0];   // [16384, 2048] fp32
    // d_in[1] (target) is unused by the reference computation.
    cudaFuncSetAttribute(ccl_kernel, cudaFuncAttributeMaxDynamicSharedMemorySize,
                         SMEM_BYTES);
    ccl_kernel<<<GRID, THREADS, SMEM_BYTES>>>(emb, (float*)d_out);
}